// round 4
// baseline (speedup 1.0000x reference)
#include <cuda_runtime.h>
#include <cuda_bf16.h>

// InternalCoordinateTransform, single kernel.
// Structure: z_mat row r = (r+3, r+2, r+1, r) => row r needs atoms r..r+3
// (floats 3r..3r+11) and writes floats 3r+9..3r+11.
// Algebra: with bond vectors e_k = A[k+1]-A[k]:
//   d21 = -e_{r+1}, d41 = e_{r+2}, b0 = -e_r
// so norms/rsqrts of e and dots D_k = e_k . e_{k+1} are shared between
// adjacent rows (rolling window over the 4-row group).

#define NDIM    7500
#define NF4     1875          // NDIM/4
#define NGROUPS 624           // rows 1..2496 in groups of 4; row 0 special
#define PI_F    3.14159265358979f
#define TWO_PI  6.28318530717959f

__device__ __forceinline__ float rsqrt_ap(float x) {
    float r; asm("rsqrt.approx.f32 %0, %1;" : "=f"(r) : "f"(x)); return r;
}
__device__ __forceinline__ float sqrt_ap(float x) {
    float r; asm("sqrt.approx.f32 %0, %1;" : "=f"(r) : "f"(x)); return r;
}
__device__ __forceinline__ float rcp_ap(float x) {
    float r; asm("rcp.approx.f32 %0, %1;" : "=f"(r) : "f"(x)); return r;
}

// Hastings-style acos, |err| ~1e-7 rad, x in [-1,1].
__device__ __forceinline__ float acos_fast(float x) {
    float xa = fabsf(x);
    float p = -0.0012624911f;
    p = fmaf(p, xa,  0.0066700901f);
    p = fmaf(p, xa, -0.0170881256f);
    p = fmaf(p, xa,  0.0308918810f);
    p = fmaf(p, xa, -0.0501743046f);
    p = fmaf(p, xa,  0.0889789874f);
    p = fmaf(p, xa, -0.2145988016f);
    p = fmaf(p, xa,  1.5707963050f);
    float r = sqrt_ap(1.0f - xa) * p;
    return (x >= 0.0f) ? r : (PI_F - r);
}

// Full-quadrant atan2, |err| ~ few e-6 rad.
__device__ __forceinline__ float atan2_fast(float y, float x) {
    float ax = fabsf(x), ay = fabsf(y);
    float mx = fmaxf(fmaxf(ax, ay), 1e-35f);
    float mn = fminf(ax, ay);
    float t  = mn * rcp_ap(mx);
    float s  = t * t;
    float p = -0.01172120f;
    p = fmaf(p, s,  0.05265332f);
    p = fmaf(p, s, -0.11643287f);
    p = fmaf(p, s,  0.19354346f);
    p = fmaf(p, s, -0.33262347f);
    p = fmaf(p, s,  0.99997726f);
    float r = t * p;
    if (ay > ax)   r = 1.57079632679f - r;
    if (x < 0.0f)  r = PI_F - r;
    return copysignf(r, y);
}

// Full generic row (used only for row 0): p3=a[0..2], p2=a[3..5], p1=a[6..8], p4=a[9..11]
__device__ __forceinline__ void ic_row(const float* a, float& bond, float& ang, float& dihe)
{
    float d21x = a[3]-a[6], d21y = a[4]-a[7], d21z = a[5]-a[8];
    float d41x = a[9]-a[6], d41y = a[10]-a[7], d41z = a[11]-a[8];
    float s21 = fmaf(d21x,d21x, fmaf(d21y,d21y, d21z*d21z));
    float s41 = fmaf(d41x,d41x, fmaf(d41y,d41y, d41z*d41z));
    float r21 = rsqrt_ap(s21), r41 = rsqrt_ap(s41);
    bond = s41 * r41;
    float dotc = fmaf(d21x,d41x, fmaf(d21y,d41y, d21z*d41z));
    float cosang = fminf(fmaxf(dotc*r21*r41, -1.0f), 1.0f);
    ang = acos_fast(cosang);
    float ux = d21x*r21, uy = d21y*r21, uz = d21z*r21;
    float b0x = a[0]-a[3], b0y = a[1]-a[4], b0z = a[2]-a[5];
    float db0 = fmaf(b0x,ux, fmaf(b0y,uy, b0z*uz));
    float vx = fmaf(-db0,ux,b0x), vy = fmaf(-db0,uy,b0y), vz = fmaf(-db0,uz,b0z);
    float db2 = fmaf(d41x,ux, fmaf(d41y,uy, d41z*uz));
    float wx = fmaf(-db2,ux,d41x), wy = fmaf(-db2,uy,d41y), wz = fmaf(-db2,uz,d41z);
    float xx = fmaf(vx,wx, fmaf(vy,wy, vz*wz));
    float cx = fmaf(uy,vz,-uz*vy), cy = fmaf(uz,vx,-ux*vz), cz = fmaf(ux,vy,-uy*vx);
    float yy = fmaf(cx,wx, fmaf(cy,wy, cz*wz));
    dihe = atan2_fast(yy, xx);
}

__global__ __launch_bounds__(256, 6)
void ict_kernel(const float* __restrict__ x,
                const float* __restrict__ mb, const float* __restrict__ sb,
                const float* __restrict__ ma, const float* __restrict__ sa,
                const float* __restrict__ md, const float* __restrict__ sd,
                float* __restrict__ out)
{
    __shared__ float4 A4[NF4];                 // the batch row, 30KB
    const int b   = blockIdx.x;
    const int tid = threadIdx.x;
    const size_t base = (size_t)b * NDIM;
    const float* A = (const float*)A4;
    float4* __restrict__ outv = (float4*)(out + base);

    // Stage row (coalesced float4).
    const float4* __restrict__ xin = (const float4*)(x + base);
#pragma unroll
    for (int k = 0; k < 8; k++) {
        int idx = tid + k * 256;
        if (idx < NF4) A4[idx] = xin[idx];
    }
    __syncthreads();

    for (int g = tid; g < NGROUPS; g += 256) {
        // atoms 4g..4g+7 -> floats 12g..12g+23 (6 aligned conflict-free LDS.128)
        float a[24];
#pragma unroll
        for (int q = 0; q < 6; q++) {
            float4 f = A4[3 * g + q];
            a[4*q] = f.x; a[4*q+1] = f.y; a[4*q+2] = f.z; a[4*q+3] = f.w;
        }

        // Rolling window init for row j=1 (rows r = 4g+j, j=1..4).
        // e_k local = A(k+1)-A(k); at row j: prev=e_j, cur=e_{j+1}, next=e_{j+2}.
        float epx = a[6]-a[3],  epy = a[7]-a[4],  epz = a[8]-a[5];    // e_1
        float ecx = a[9]-a[6],  ecy = a[10]-a[7], ecz = a[11]-a[8];   // e_2
        float Sc  = fmaf(ecx,ecx, fmaf(ecy,ecy, ecz*ecz));
        float Rc  = rsqrt_ap(Sc);
        float Dp  = fmaf(epx,ecx, fmaf(epy,ecy, epz*ecz));           // D_1

        float res[12];
#pragma unroll
        for (int j = 1; j <= 4; j++) {
            // e_next = e_{j+2} = A(j+3)-A(j+2): floats 3(j+3)..  -  3(j+2)..
            const float* An2 = a + 3*(j+2);
            const float* An3 = a + 3*(j+3);
            float enx = An3[0]-An2[0], eny = An3[1]-An2[1], enz = An3[2]-An2[2];
            float Sn  = fmaf(enx,enx, fmaf(eny,eny, enz*enz));
            float Rn  = rsqrt_ap(Sn);
            float Dc  = fmaf(ecx,enx, fmaf(ecy,eny, ecz*enz));       // D_{j+1}

            float bond = Sn * Rn;

            float cosang = fminf(fmaxf(-Dc * Rc * Rn, -1.0f), 1.0f);
            float ang = acos_fast(cosang);

            float inv = Rc * Rc;                 // 1/S_cur
            float f0 = Dp * inv;
            float f1 = Dc * inv;
            // v' = e_prev - f0 e_cur (true v = -v');  w = e_next - f1 e_cur
            float vx = fmaf(-f0, ecx, epx), vy = fmaf(-f0, ecy, epy), vz = fmaf(-f0, ecz, epz);
            float wx = fmaf(-f1, ecx, enx), wy = fmaf(-f1, ecy, eny), wz = fmaf(-f1, ecz, enz);

            float xx = -fmaf(vx,wx, fmaf(vy,wy, vz*wz));
            // cross(e_cur, v')
            float cx = fmaf(ecy,vz, -ecz*vy);
            float cy = fmaf(ecz,vx, -ecx*vz);
            float cz = fmaf(ecx,vy, -ecy*vx);
            float yy = Rc * fmaf(cx,wx, fmaf(cy,wy, cz*wz));
            float dihe = atan2_fast(yy, xx);

            // normalize (params inline, L2-resident)
            int r = 4*g + j;
            float ob = (bond - __ldg(mb + r)) * rcp_ap(__ldg(sb + r));
            float oa = (ang  - __ldg(ma + r)) * rcp_ap(__ldg(sa + r));
            float dd = dihe - __ldg(md + r);
            dd = (dd < -PI_F) ? dd + TWO_PI : dd;
            dd = (dd >  PI_F) ? dd - TWO_PI : dd;
            float od = dd * rcp_ap(__ldg(sd + r));

            res[3*(j-1)]   = ob;
            res[3*(j-1)+1] = oa;
            res[3*(j-1)+2] = od;

            // shift window
            epx = ecx; epy = ecy; epz = ecz;
            ecx = enx; ecy = eny; ecz = enz;
            Sc = Sn; Rc = Rn; Dp = Dc;
        }

        outv[3*g + 3] = make_float4(res[0], res[1], res[2],  res[3]);
        outv[3*g + 4] = make_float4(res[4], res[5], res[6],  res[7]);
        outv[3*g + 5] = make_float4(res[8], res[9], res[10], res[11]);
    }

    // Row 0 + head (floats 0..11): one thread, 3 aligned STG.128.
    if (tid == 255) {
        float bond, ang, dihe;
        ic_row(A, bond, ang, dihe);
        float ob = (bond - __ldg(mb)) * rcp_ap(__ldg(sb));
        float oa = (ang  - __ldg(ma)) * rcp_ap(__ldg(sa));
        float dd = dihe - __ldg(md);
        dd = (dd < -PI_F) ? dd + TWO_PI : dd;
        dd = (dd >  PI_F) ? dd - TWO_PI : dd;
        float od = dd * rcp_ap(__ldg(sd));
        outv[0] = make_float4(A[0], A[1], A[2], A[3]);
        outv[1] = make_float4(A[4], A[5], A[6], A[7]);
        outv[2] = make_float4(A[8], ob, oa, od);
    }
}

extern "C" void kernel_launch(void* const* d_in, const int* in_sizes, int n_in,
                              void* d_out, int out_size)
{
    const float* x  = (const float*)d_in[0];
    const float* mb = (const float*)d_in[2];
    const float* sb = (const float*)d_in[3];
    const float* ma = (const float*)d_in[4];
    const float* sa = (const float*)d_in[5];
    const float* md = (const float*)d_in[6];
    const float* sd = (const float*)d_in[7];

    int bsz = in_sizes[0] / NDIM;   // 2048

    ict_kernel<<<bsz, 256>>>(x, mb, sb, ma, sa, md, sd, (float*)d_out);
}

// round 5
// speedup vs baseline: 1.0809x; 1.0809x over previous
#include <cuda_runtime.h>
#include <cuda_bf16.h>

// InternalCoordinateTransform, single kernel.
// Structure: z_mat row r = (r+3, r+2, r+1, r) => row r needs atoms r..r+3
// (floats 3r..3r+11) and writes floats 3r+9..3r+11.
// Algebra: with bond vectors e_k = A[k+1]-A[k]:
//   d21 = -e_{r+1}, d41 = e_{r+2}, b0 = -e_r
// so norms/rsqrts of e and dots D_k = e_k . e_{k+1} are shared between
// adjacent rows (rolling window over the 4-row group).
// NOTE (R4 post-mortem): do NOT cap registers — a 40-reg cap spills the
// a[24]/res[12] working set to local memory and regresses 28.8 -> 38.5 us.

#define NDIM    7500
#define NF4     1875          // NDIM/4
#define NGROUPS 624           // rows 1..2496 in groups of 4; row 0 special
#define PI_F    3.14159265358979f
#define TWO_PI  6.28318530717959f

__device__ __forceinline__ float rsqrt_ap(float x) {
    float r; asm("rsqrt.approx.f32 %0, %1;" : "=f"(r) : "f"(x)); return r;
}
__device__ __forceinline__ float sqrt_ap(float x) {
    float r; asm("sqrt.approx.f32 %0, %1;" : "=f"(r) : "f"(x)); return r;
}
__device__ __forceinline__ float rcp_ap(float x) {
    float r; asm("rcp.approx.f32 %0, %1;" : "=f"(r) : "f"(x)); return r;
}

// Hastings-style acos, |err| ~1e-7 rad, x in [-1,1].
__device__ __forceinline__ float acos_fast(float x) {
    float xa = fabsf(x);
    float p = -0.0012624911f;
    p = fmaf(p, xa,  0.0066700901f);
    p = fmaf(p, xa, -0.0170881256f);
    p = fmaf(p, xa,  0.0308918810f);
    p = fmaf(p, xa, -0.0501743046f);
    p = fmaf(p, xa,  0.0889789874f);
    p = fmaf(p, xa, -0.2145988016f);
    p = fmaf(p, xa,  1.5707963050f);
    float r = sqrt_ap(1.0f - xa) * p;
    return (x >= 0.0f) ? r : (PI_F - r);
}

// Full-quadrant atan2, |err| ~ few e-6 rad.
__device__ __forceinline__ float atan2_fast(float y, float x) {
    float ax = fabsf(x), ay = fabsf(y);
    float mx = fmaxf(fmaxf(ax, ay), 1e-35f);
    float mn = fminf(ax, ay);
    float t  = mn * rcp_ap(mx);
    float s  = t * t;
    float p = -0.01172120f;
    p = fmaf(p, s,  0.05265332f);
    p = fmaf(p, s, -0.11643287f);
    p = fmaf(p, s,  0.19354346f);
    p = fmaf(p, s, -0.33262347f);
    p = fmaf(p, s,  0.99997726f);
    float r = t * p;
    if (ay > ax)   r = 1.57079632679f - r;
    if (x < 0.0f)  r = PI_F - r;
    return copysignf(r, y);
}

// Full generic row (used only for row 0): p3=a[0..2], p2=a[3..5], p1=a[6..8], p4=a[9..11]
__device__ __forceinline__ void ic_row(const float* a, float& bond, float& ang, float& dihe)
{
    float d21x = a[3]-a[6], d21y = a[4]-a[7], d21z = a[5]-a[8];
    float d41x = a[9]-a[6], d41y = a[10]-a[7], d41z = a[11]-a[8];
    float s21 = fmaf(d21x,d21x, fmaf(d21y,d21y, d21z*d21z));
    float s41 = fmaf(d41x,d41x, fmaf(d41y,d41y, d41z*d41z));
    float r21 = rsqrt_ap(s21), r41 = rsqrt_ap(s41);
    bond = s41 * r41;
    float dotc = fmaf(d21x,d41x, fmaf(d21y,d41y, d21z*d41z));
    float cosang = fminf(fmaxf(dotc*r21*r41, -1.0f), 1.0f);
    ang = acos_fast(cosang);
    float ux = d21x*r21, uy = d21y*r21, uz = d21z*r21;
    float b0x = a[0]-a[3], b0y = a[1]-a[4], b0z = a[2]-a[5];
    float db0 = fmaf(b0x,ux, fmaf(b0y,uy, b0z*uz));
    float vx = fmaf(-db0,ux,b0x), vy = fmaf(-db0,uy,b0y), vz = fmaf(-db0,uz,b0z);
    float db2 = fmaf(d41x,ux, fmaf(d41y,uy, d41z*uz));
    float wx = fmaf(-db2,ux,d41x), wy = fmaf(-db2,uy,d41y), wz = fmaf(-db2,uz,d41z);
    float xx = fmaf(vx,wx, fmaf(vy,wy, vz*wz));
    float cx = fmaf(uy,vz,-uz*vy), cy = fmaf(uz,vx,-ux*vz), cz = fmaf(ux,vy,-uy*vx);
    float yy = fmaf(cx,wx, fmaf(cy,wy, cz*wz));
    dihe = atan2_fast(yy, xx);
}

__global__ __launch_bounds__(256)
void ict_kernel(const float* __restrict__ x,
                const float* __restrict__ mb, const float* __restrict__ sb,
                const float* __restrict__ ma, const float* __restrict__ sa,
                const float* __restrict__ md, const float* __restrict__ sd,
                float* __restrict__ out)
{
    __shared__ float4 A4[NF4];                 // the batch row, 30KB
    const int b   = blockIdx.x;
    const int tid = threadIdx.x;
    const size_t base = (size_t)b * NDIM;
    const float* A = (const float*)A4;
    float4* __restrict__ outv = (float4*)(out + base);

    // Stage row (coalesced float4).
    const float4* __restrict__ xin = (const float4*)(x + base);
#pragma unroll
    for (int k = 0; k < 8; k++) {
        int idx = tid + k * 256;
        if (idx < NF4) A4[idx] = xin[idx];
    }
    __syncthreads();

    for (int g = tid; g < NGROUPS; g += 256) {
        // atoms 4g..4g+7 -> floats 12g..12g+23 (6 aligned conflict-free LDS.128)
        float a[24];
#pragma unroll
        for (int q = 0; q < 6; q++) {
            float4 f = A4[3 * g + q];
            a[4*q] = f.x; a[4*q+1] = f.y; a[4*q+2] = f.z; a[4*q+3] = f.w;
        }

        // Rolling window init for row j=1 (rows r = 4g+j, j=1..4).
        // e_k local = A(k+1)-A(k); at row j: prev=e_j, cur=e_{j+1}, next=e_{j+2}.
        float epx = a[6]-a[3],  epy = a[7]-a[4],  epz = a[8]-a[5];    // e_1
        float ecx = a[9]-a[6],  ecy = a[10]-a[7], ecz = a[11]-a[8];   // e_2
        float Sc  = fmaf(ecx,ecx, fmaf(ecy,ecy, ecz*ecz));
        float Rc  = rsqrt_ap(Sc);
        float Dp  = fmaf(epx,ecx, fmaf(epy,ecy, epz*ecz));           // D_1

        float res[12];
#pragma unroll
        for (int j = 1; j <= 4; j++) {
            // e_next = e_{j+2} = A(j+3)-A(j+2)
            const float* An2 = a + 3*(j+2);
            const float* An3 = a + 3*(j+3);
            float enx = An3[0]-An2[0], eny = An3[1]-An2[1], enz = An3[2]-An2[2];
            float Sn  = fmaf(enx,enx, fmaf(eny,eny, enz*enz));
            float Rn  = rsqrt_ap(Sn);
            float Dc  = fmaf(ecx,enx, fmaf(ecy,eny, ecz*enz));       // D_{j+1}

            float bond = Sn * Rn;

            float cosang = fminf(fmaxf(-Dc * Rc * Rn, -1.0f), 1.0f);
            float ang = acos_fast(cosang);

            float inv = Rc * Rc;                 // 1/S_cur
            float f0 = Dp * inv;
            float f1 = Dc * inv;
            // v' = e_prev - f0 e_cur (true v = -v');  w = e_next - f1 e_cur
            float vx = fmaf(-f0, ecx, epx), vy = fmaf(-f0, ecy, epy), vz = fmaf(-f0, ecz, epz);
            float wx = fmaf(-f1, ecx, enx), wy = fmaf(-f1, ecy, eny), wz = fmaf(-f1, ecz, enz);

            float xx = -fmaf(vx,wx, fmaf(vy,wy, vz*wz));
            // cross(e_cur, v')
            float cx = fmaf(ecy,vz, -ecz*vy);
            float cy = fmaf(ecz,vx, -ecx*vz);
            float cz = fmaf(ecx,vy, -ecy*vx);
            float yy = Rc * fmaf(cx,wx, fmaf(cy,wy, cz*wz));
            float dihe = atan2_fast(yy, xx);

            // normalize (params inline, L2-resident)
            int r = 4*g + j;
            float ob = (bond - __ldg(mb + r)) * rcp_ap(__ldg(sb + r));
            float oa = (ang  - __ldg(ma + r)) * rcp_ap(__ldg(sa + r));
            float dd = dihe - __ldg(md + r);
            dd = (dd < -PI_F) ? dd + TWO_PI : dd;
            dd = (dd >  PI_F) ? dd - TWO_PI : dd;
            float od = dd * rcp_ap(__ldg(sd + r));

            res[3*(j-1)]   = ob;
            res[3*(j-1)+1] = oa;
            res[3*(j-1)+2] = od;

            // shift window
            epx = ecx; epy = ecy; epz = ecz;
            ecx = enx; ecy = eny; ecz = enz;
            Sc = Sn; Rc = Rn; Dp = Dc;
        }

        outv[3*g + 3] = make_float4(res[0], res[1], res[2],  res[3]);
        outv[3*g + 4] = make_float4(res[4], res[5], res[6],  res[7]);
        outv[3*g + 5] = make_float4(res[8], res[9], res[10], res[11]);
    }

    // Row 0 + head (floats 0..11): one thread, 3 aligned STG.128.
    if (tid == 255) {
        float bond, ang, dihe;
        ic_row(A, bond, ang, dihe);
        float ob = (bond - __ldg(mb)) * rcp_ap(__ldg(sb));
        float oa = (ang  - __ldg(ma)) * rcp_ap(__ldg(sa));
        float dd = dihe - __ldg(md);
        dd = (dd < -PI_F) ? dd + TWO_PI : dd;
        dd = (dd >  PI_F) ? dd - TWO_PI : dd;
        float od = dd * rcp_ap(__ldg(sd));
        outv[0] = make_float4(A[0], A[1], A[2], A[3]);
        outv[1] = make_float4(A[4], A[5], A[6], A[7]);
        outv[2] = make_float4(A[8], ob, oa, od);
    }
}

extern "C" void kernel_launch(void* const* d_in, const int* in_sizes, int n_in,
                              void* d_out, int out_size)
{
    const float* x  = (const float*)d_in[0];
    const float* mb = (const float*)d_in[2];
    const float* sb = (const float*)d_in[3];
    const float* ma = (const float*)d_in[4];
    const float* sa = (const float*)d_in[5];
    const float* md = (const float*)d_in[6];
    const float* sd = (const float*)d_in[7];

    int bsz = in_sizes[0] / NDIM;   // 2048

    ict_kernel<<<bsz, 256>>>(x, mb, sb, ma, sa, md, sd, (float*)d_out);
}

// round 7
// speedup vs baseline: 1.1633x; 1.0762x over previous
#include <cuda_runtime.h>
#include <cuda_bf16.h>

// InternalCoordinateTransform, single kernel, no prep pass.
// Structure: z_mat row r = (r+3, r+2, r+1, r) => row r needs atoms r..r+3
// (floats 3r..3r+11) and writes floats 3r+9..3r+11.
// Thread g handles rows 4g+1..4g+4: loads atoms 4g..4g+7 as 6 aligned LDS.128,
// stores results as 3 aligned STG.128.
// Params (6 arrays, rows 4g+1..4g+4, misaligned by 1): load the ALIGNED float4
// at element 4g and obtain row 4g+4's value from lane+1 via __shfl_down
// (lane 31 / boundary: scalar fallback). 6 LDG.128 per group, like packed.
// Geometry uses bond vectors e_k = atom(k+1)-atom(k); norms/rsqrts and
// adjacent dots are shared between rows (rolling window).
// R4 lesson: no register cap (spills). R5 lesson: no per-row scalar LDGs.

#define NDIM    7500
#define NF4     1875          // NDIM/4
#define NGROUPS 624           // rows 1..2496 in groups of 4; row 0 special
#define PI_F    3.14159265358979f
#define TWO_PI  6.28318530717959f

__device__ __forceinline__ float rsqrt_ap(float x) {
    float r; asm("rsqrt.approx.f32 %0, %1;" : "=f"(r) : "f"(x)); return r;
}
__device__ __forceinline__ float sqrt_ap(float x) {
    float r; asm("sqrt.approx.f32 %0, %1;" : "=f"(r) : "f"(x)); return r;
}
__device__ __forceinline__ float rcp_ap(float x) {
    float r; asm("rcp.approx.f32 %0, %1;" : "=f"(r) : "f"(x)); return r;
}

// Hastings-style acos, |err| ~1e-7 rad, x in [-1,1].
__device__ __forceinline__ float acos_fast(float x) {
    float xa = fabsf(x);
    float p = -0.0012624911f;
    p = fmaf(p, xa,  0.0066700901f);
    p = fmaf(p, xa, -0.0170881256f);
    p = fmaf(p, xa,  0.0308918810f);
    p = fmaf(p, xa, -0.0501743046f);
    p = fmaf(p, xa,  0.0889789874f);
    p = fmaf(p, xa, -0.2145988016f);
    p = fmaf(p, xa,  1.5707963050f);
    float r = sqrt_ap(1.0f - xa) * p;
    return (x >= 0.0f) ? r : (PI_F - r);
}

// Full-quadrant atan2, |err| ~ few e-6 rad.
__device__ __forceinline__ float atan2_fast(float y, float x) {
    float ax = fabsf(x), ay = fabsf(y);
    float mx = fmaxf(fmaxf(ax, ay), 1e-35f);
    float mn = fminf(ax, ay);
    float t  = mn * rcp_ap(mx);
    float s  = t * t;
    float p = -0.01172120f;
    p = fmaf(p, s,  0.05265332f);
    p = fmaf(p, s, -0.11643287f);
    p = fmaf(p, s,  0.19354346f);
    p = fmaf(p, s, -0.33262347f);
    p = fmaf(p, s,  0.99997726f);
    float r = t * p;
    if (ay > ax)   r = 1.57079632679f - r;
    if (x < 0.0f)  r = PI_F - r;
    return copysignf(r, y);
}

// Generic row (row 0 only): p3=a[0..2], p2=a[3..5], p1=a[6..8], p4=a[9..11]
__device__ __forceinline__ void ic_row(const float* a, float& bond, float& ang, float& dihe)
{
    float d21x = a[3]-a[6], d21y = a[4]-a[7], d21z = a[5]-a[8];
    float d41x = a[9]-a[6], d41y = a[10]-a[7], d41z = a[11]-a[8];
    float s21 = fmaf(d21x,d21x, fmaf(d21y,d21y, d21z*d21z));
    float s41 = fmaf(d41x,d41x, fmaf(d41y,d41y, d41z*d41z));
    float r21 = rsqrt_ap(s21), r41 = rsqrt_ap(s41);
    bond = s41 * r41;
    float dotc = fmaf(d21x,d41x, fmaf(d21y,d41y, d21z*d41z));
    float cosang = fminf(fmaxf(dotc*r21*r41, -1.0f), 1.0f);
    ang = acos_fast(cosang);
    float ux = d21x*r21, uy = d21y*r21, uz = d21z*r21;
    float b0x = a[0]-a[3], b0y = a[1]-a[4], b0z = a[2]-a[5];
    float db0 = fmaf(b0x,ux, fmaf(b0y,uy, b0z*uz));
    float vx = fmaf(-db0,ux,b0x), vy = fmaf(-db0,uy,b0y), vz = fmaf(-db0,uz,b0z);
    float db2 = fmaf(d41x,ux, fmaf(d41y,uy, d41z*uz));
    float wx = fmaf(-db2,ux,d41x), wy = fmaf(-db2,uy,d41y), wz = fmaf(-db2,uz,d41z);
    float xx = fmaf(vx,wx, fmaf(vy,wy, vz*wz));
    float cx = fmaf(uy,vz,-uz*vy), cy = fmaf(uz,vx,-ux*vz), cz = fmaf(ux,vy,-uy*vx);
    float yy = fmaf(cx,wx, fmaf(cy,wy, cz*wz));
    dihe = atan2_fast(yy, xx);
}

__global__ __launch_bounds__(256)
void ict_kernel(const float* __restrict__ x,
                const float* __restrict__ mb, const float* __restrict__ sb,
                const float* __restrict__ ma, const float* __restrict__ sa,
                const float* __restrict__ md, const float* __restrict__ sd,
                float* __restrict__ out)
{
    __shared__ float4 A4[NF4];                 // the batch row, 30KB
    const int b   = blockIdx.x;
    const int tid = threadIdx.x;
    const size_t base = (size_t)b * NDIM;
    const float* A = (const float*)A4;
    float4* __restrict__ outv = (float4*)(out + base);

    // Stage row (coalesced float4).
    const float4* __restrict__ xin = (const float4*)(x + base);
#pragma unroll
    for (int k = 0; k < 8; k++) {
        int idx = tid + k * 256;
        if (idx < NF4) A4[idx] = xin[idx];
    }
    __syncthreads();

    const float4* __restrict__ mb4 = (const float4*)mb;
    const float4* __restrict__ sb4 = (const float4*)sb;
    const float4* __restrict__ ma4 = (const float4*)ma;
    const float4* __restrict__ sa4 = (const float4*)sa;
    const float4* __restrict__ md4 = (const float4*)md;
    const float4* __restrict__ sd4 = (const float4*)sd;

    for (int g = tid; g < NGROUPS; g += 256) {
        // ---- atoms 4g..4g+7 = floats 12g..12g+23: 6 aligned LDS.128 ----
        float4 f0 = A4[3*g],   f1 = A4[3*g+1], f2 = A4[3*g+2];
        float4 f3 = A4[3*g+3], f4 = A4[3*g+4], f5 = A4[3*g+5];

        // bond vectors e_k = atom(4g+k+1) - atom(4g+k), k=1..6
        // atoms: a1=(f0.w,f1.x,f1.y) a2=(f1.z,f1.w,f2.x) a3=(f2.y,f2.z,f2.w)
        //        a4=(f3.x,f3.y,f3.z) a5=(f3.w,f4.x,f4.y) a6=(f4.z,f4.w,f5.x)
        //        a7=(f5.y,f5.z,f5.w)
        float ex[7], ey[7], ez[7];
        ex[1] = f1.z - f0.w; ey[1] = f1.w - f1.x; ez[1] = f2.x - f1.y;
        ex[2] = f2.y - f1.z; ey[2] = f2.z - f1.w; ez[2] = f2.w - f2.x;
        ex[3] = f3.x - f2.y; ey[3] = f3.y - f2.z; ez[3] = f3.z - f2.w;
        ex[4] = f3.w - f3.x; ey[4] = f4.x - f3.y; ez[4] = f4.y - f3.z;
        ex[5] = f4.z - f3.w; ey[5] = f4.w - f4.x; ez[5] = f5.x - f4.y;
        ex[6] = f5.y - f4.z; ey[6] = f5.z - f4.w; ez[6] = f5.w - f5.x;

        // ---- params: aligned float4 at element 4g (rows 4g..4g+3),
        //      row 4g+4 from lane+1 via shuffle (boundary: scalar) ----
        float4 qmb = __ldg(mb4 + g), qsb = __ldg(sb4 + g);
        float4 qma = __ldg(ma4 + g), qsa = __ldg(sa4 + g);
        float4 qmd = __ldg(md4 + g), qsd = __ldg(sd4 + g);
        unsigned msk = __activemask();
        float nmb = __shfl_down_sync(msk, qmb.x, 1);
        float nsb = __shfl_down_sync(msk, qsb.x, 1);
        float nma = __shfl_down_sync(msk, qma.x, 1);
        float nsa = __shfl_down_sync(msk, qsa.x, 1);
        float nmd = __shfl_down_sync(msk, qmd.x, 1);
        float nsd = __shfl_down_sync(msk, qsd.x, 1);
        if (((tid & 31) == 31) || (g + 1 >= NGROUPS)) {
            int r4 = 4*g + 4;
            nmb = __ldg(mb + r4); nsb = __ldg(sb + r4);
            nma = __ldg(ma + r4); nsa = __ldg(sa + r4);
            nmd = __ldg(md + r4); nsd = __ldg(sd + r4);
        }
        float pmb[4] = {qmb.y, qmb.z, qmb.w, nmb};
        float psb[4] = {qsb.y, qsb.z, qsb.w, nsb};
        float pma[4] = {qma.y, qma.z, qma.w, nma};
        float psa[4] = {qsa.y, qsa.z, qsa.w, nsa};
        float pmd[4] = {qmd.y, qmd.z, qmd.w, nmd};
        float psd[4] = {qsd.y, qsd.z, qsd.w, nsd};

        // ---- rolling window over rows r = 4g+j, j=1..4 ----
        float Rc = rsqrt_ap(fmaf(ex[2],ex[2], fmaf(ey[2],ey[2], ez[2]*ez[2])));
        float Dp = fmaf(ex[1],ex[2], fmaf(ey[1],ey[2], ez[1]*ez[2]));

        float res[12];
#pragma unroll
        for (int j = 1; j <= 4; j++) {
            float pxc = ex[j],   pyc = ey[j],   pzc = ez[j];     // prev = e_j
            float cxe = ex[j+1], cye = ey[j+1], cze = ez[j+1];   // cur  = e_{j+1}
            float nxe = ex[j+2], nye = ey[j+2], nze = ez[j+2];   // next = e_{j+2}

            float Sn = fmaf(nxe,nxe, fmaf(nye,nye, nze*nze));
            float Rn = rsqrt_ap(Sn);
            float Dc = fmaf(cxe,nxe, fmaf(cye,nye, cze*nze));

            float bond = Sn * Rn;

            float cosang = fminf(fmaxf(-Dc * Rc * Rn, -1.0f), 1.0f);
            float ang = acos_fast(cosang);

            float inv = Rc * Rc;                 // 1/|e_cur|^2
            float f0c = Dp * inv;
            float f1c = Dc * inv;
            // v' = prev - f0*cur (true v = -v');  w = next - f1*cur
            float vx = fmaf(-f0c, cxe, pxc), vy = fmaf(-f0c, cye, pyc), vz = fmaf(-f0c, cze, pzc);
            float wx = fmaf(-f1c, cxe, nxe), wy = fmaf(-f1c, cye, nye), wz = fmaf(-f1c, cze, nze);

            float xx = -fmaf(vx,wx, fmaf(vy,wy, vz*wz));
            float cxx = fmaf(cye,vz, -cze*vy);
            float cyy = fmaf(cze,vx, -cxe*vz);
            float czz = fmaf(cxe,vy, -cye*vx);
            float yy = Rc * fmaf(cxx,wx, fmaf(cyy,wy, czz*wz));
            float dihe = atan2_fast(yy, xx);

            float ob = (bond - pmb[j-1]) * rcp_ap(psb[j-1]);
            float oa = (ang  - pma[j-1]) * rcp_ap(psa[j-1]);
            float dd = dihe - pmd[j-1];
            dd = (dd < -PI_F) ? dd + TWO_PI : dd;
            dd = (dd >  PI_F) ? dd - TWO_PI : dd;
            float od = dd * rcp_ap(psd[j-1]);

            res[3*(j-1)]   = ob;
            res[3*(j-1)+1] = oa;
            res[3*(j-1)+2] = od;

            Rc = Rn; Dp = Dc;
        }

        outv[3*g + 3] = make_float4(res[0], res[1], res[2],  res[3]);
        outv[3*g + 4] = make_float4(res[4], res[5], res[6],  res[7]);
        outv[3*g + 5] = make_float4(res[8], res[9], res[10], res[11]);
    }

    // Row 0 + head (floats 0..11): one thread, 3 aligned STG.128.
    if (tid == 255) {
        float bond, ang, dihe;
        ic_row(A, bond, ang, dihe);
        float ob = (bond - __ldg(mb)) * rcp_ap(__ldg(sb));
        float oa = (ang  - __ldg(ma)) * rcp_ap(__ldg(sa));
        float dd = dihe - __ldg(md);
        dd = (dd < -PI_F) ? dd + TWO_PI : dd;
        dd = (dd >  PI_F) ? dd - TWO_PI : dd;
        float od = dd * rcp_ap(__ldg(sd));
        outv[0] = make_float4(A[0], A[1], A[2], A[3]);
        outv[1] = make_float4(A[4], A[5], A[6], A[7]);
        outv[2] = make_float4(A[8], ob, oa, od);
    }
}

extern "C" void kernel_launch(void* const* d_in, const int* in_sizes, int n_in,
                              void* d_out, int out_size)
{
    const float* x  = (const float*)d_in[0];
    const float* mb = (const float*)d_in[2];
    const float* sb = (const float*)d_in[3];
    const float* ma = (const float*)d_in[4];
    const float* sa = (const float*)d_in[5];
    const float* md = (const float*)d_in[6];
    const float* sd = (const float*)d_in[7];

    int bsz = in_sizes[0] / NDIM;   // 2048

    ict_kernel<<<bsz, 256>>>(x, mb, sb, ma, sa, md, sd, (float*)d_out);
}

// round 8
// speedup vs baseline: 1.1772x; 1.0119x over previous
#include <cuda_runtime.h>
#include <cuda_bf16.h>

// InternalCoordinateTransform.
// Structure: z_mat row r = (r+3, r+2, r+1, r) => row r needs atoms r..r+3
// (floats 3r..3r+11) and writes floats 3r+9..3r+11. Thread g handles rows
// 4g+1..4g+4 (atoms 4g..4g+7 = 6 aligned LDS.128; results = 3 aligned STG.128).
// Params pre-packed by a tiny prep kernel into group-SoA float4s (6 LDG.128
// per group, no MUFU in hot loop for normalization).
// Geometry via bond vectors e_k = atom(k+1)-atom(k): rolling window shares
// rsqrt/norm/dot between adjacent rows (5 rsqrt per group instead of 8).
// Lessons: R4 no reg cap (spills); R5 no scalar per-row param LDG; R7 no shuffle.

#define NDIM    7500
#define NF4     1875          // NDIM/4
#define NGROUPS 624           // rows 1..2496 in groups of 4; row 0 special
#define PI_F    3.14159265358979f
#define TWO_PI  6.28318530717959f

// Group-SoA packed params, k=0..5: {isb}, {-mb*isb}, {isa}, {-ma*isa}, {md}, {isd}
__device__ float4 g_prm[6 * NGROUPS];

__device__ __forceinline__ float rsqrt_ap(float x) {
    float r; asm("rsqrt.approx.f32 %0, %1;" : "=f"(r) : "f"(x)); return r;
}
__device__ __forceinline__ float sqrt_ap(float x) {
    float r; asm("sqrt.approx.f32 %0, %1;" : "=f"(r) : "f"(x)); return r;
}
__device__ __forceinline__ float rcp_ap(float x) {
    float r; asm("rcp.approx.f32 %0, %1;" : "=f"(r) : "f"(x)); return r;
}

// Hastings-style acos, |err| ~1e-7 rad, x in [-1,1].
__device__ __forceinline__ float acos_fast(float x) {
    float xa = fabsf(x);
    float p = -0.0012624911f;
    p = fmaf(p, xa,  0.0066700901f);
    p = fmaf(p, xa, -0.0170881256f);
    p = fmaf(p, xa,  0.0308918810f);
    p = fmaf(p, xa, -0.0501743046f);
    p = fmaf(p, xa,  0.0889789874f);
    p = fmaf(p, xa, -0.2145988016f);
    p = fmaf(p, xa,  1.5707963050f);
    float r = sqrt_ap(1.0f - xa) * p;
    return (x >= 0.0f) ? r : (PI_F - r);
}

// Full-quadrant atan2, |err| ~ few e-6 rad.
__device__ __forceinline__ float atan2_fast(float y, float x) {
    float ax = fabsf(x), ay = fabsf(y);
    float mx = fmaxf(fmaxf(ax, ay), 1e-35f);
    float mn = fminf(ax, ay);
    float t  = mn * rcp_ap(mx);
    float s  = t * t;
    float p = -0.01172120f;
    p = fmaf(p, s,  0.05265332f);
    p = fmaf(p, s, -0.11643287f);
    p = fmaf(p, s,  0.19354346f);
    p = fmaf(p, s, -0.33262347f);
    p = fmaf(p, s,  0.99997726f);
    float r = t * p;
    if (ay > ax)   r = 1.57079632679f - r;
    if (x < 0.0f)  r = PI_F - r;
    return copysignf(r, y);
}

// Generic row (row 0 only): p3=a[0..2], p2=a[3..5], p1=a[6..8], p4=a[9..11]
__device__ __forceinline__ void ic_row(const float* a, float& bond, float& ang, float& dihe)
{
    float d21x = a[3]-a[6], d21y = a[4]-a[7], d21z = a[5]-a[8];
    float d41x = a[9]-a[6], d41y = a[10]-a[7], d41z = a[11]-a[8];
    float s21 = fmaf(d21x,d21x, fmaf(d21y,d21y, d21z*d21z));
    float s41 = fmaf(d41x,d41x, fmaf(d41y,d41y, d41z*d41z));
    float r21 = rsqrt_ap(s21), r41 = rsqrt_ap(s41);
    bond = s41 * r41;
    float dotc = fmaf(d21x,d41x, fmaf(d21y,d41y, d21z*d41z));
    float cosang = fminf(fmaxf(dotc*r21*r41, -1.0f), 1.0f);
    ang = acos_fast(cosang);
    float ux = d21x*r21, uy = d21y*r21, uz = d21z*r21;
    float b0x = a[0]-a[3], b0y = a[1]-a[4], b0z = a[2]-a[5];
    float db0 = fmaf(b0x,ux, fmaf(b0y,uy, b0z*uz));
    float vx = fmaf(-db0,ux,b0x), vy = fmaf(-db0,uy,b0y), vz = fmaf(-db0,uz,b0z);
    float db2 = fmaf(d41x,ux, fmaf(d41y,uy, d41z*uz));
    float wx = fmaf(-db2,ux,d41x), wy = fmaf(-db2,uy,d41y), wz = fmaf(-db2,uz,d41z);
    float xx = fmaf(vx,wx, fmaf(vy,wy, vz*wz));
    float cx = fmaf(uy,vz,-uz*vy), cy = fmaf(uz,vx,-ux*vz), cz = fmaf(ux,vy,-uy*vx);
    float yy = fmaf(cx,wx, fmaf(cy,wy, cz*wz));
    dihe = atan2_fast(yy, xx);
}

__global__ void prep_kernel(const float* __restrict__ mb, const float* __restrict__ sb,
                            const float* __restrict__ ma, const float* __restrict__ sa,
                            const float* __restrict__ md, const float* __restrict__ sd)
{
    int g = blockIdx.x * blockDim.x + threadIdx.x;
    if (g >= NGROUPS) return;
    float4 v0, v1, v2, v3, v4, v5;
    float* p0 = (float*)&v0; float* p1 = (float*)&v1; float* p2 = (float*)&v2;
    float* p3 = (float*)&v3; float* p4 = (float*)&v4; float* p5 = (float*)&v5;
#pragma unroll
    for (int j = 0; j < 4; j++) {
        int r = 4 * g + 1 + j;
        float isb = rcp_ap(sb[r]);
        float isa = rcp_ap(sa[r]);
        float isd = rcp_ap(sd[r]);
        p0[j] = isb;   p1[j] = -mb[r] * isb;
        p2[j] = isa;   p3[j] = -ma[r] * isa;
        p4[j] = md[r]; p5[j] = isd;
    }
    g_prm[0 * NGROUPS + g] = v0;
    g_prm[1 * NGROUPS + g] = v1;
    g_prm[2 * NGROUPS + g] = v2;
    g_prm[3 * NGROUPS + g] = v3;
    g_prm[4 * NGROUPS + g] = v4;
    g_prm[5 * NGROUPS + g] = v5;
}

__global__ __launch_bounds__(256)
void ict_kernel(const float* __restrict__ x,
                const float* __restrict__ mb, const float* __restrict__ sb,
                const float* __restrict__ ma, const float* __restrict__ sa,
                const float* __restrict__ md, const float* __restrict__ sd,
                float* __restrict__ out)
{
    __shared__ float4 A4[NF4];                 // the batch row, 30KB
    const int b   = blockIdx.x;
    const int tid = threadIdx.x;
    const size_t base = (size_t)b * NDIM;
    const float* A = (const float*)A4;
    float4* __restrict__ outv = (float4*)(out + base);

    // Stage row (coalesced float4).
    const float4* __restrict__ xin = (const float4*)(x + base);
#pragma unroll
    for (int k = 0; k < 8; k++) {
        int idx = tid + k * 256;
        if (idx < NF4) A4[idx] = xin[idx];
    }
    __syncthreads();

    for (int g = tid; g < NGROUPS; g += 256) {
        // ---- atoms 4g..4g+7 = floats 12g..12g+23: 6 aligned LDS.128 ----
        float4 f0 = A4[3*g],   f1 = A4[3*g+1], f2 = A4[3*g+2];
        float4 f3 = A4[3*g+3], f4 = A4[3*g+4], f5 = A4[3*g+5];

        // bond vectors e_k = atom(4g+k+1) - atom(4g+k), k=1..6
        float ex[7], ey[7], ez[7];
        ex[1] = f1.z - f0.w; ey[1] = f1.w - f1.x; ez[1] = f2.x - f1.y;
        ex[2] = f2.y - f1.z; ey[2] = f2.z - f1.w; ez[2] = f2.w - f2.x;
        ex[3] = f3.x - f2.y; ey[3] = f3.y - f2.z; ez[3] = f3.z - f2.w;
        ex[4] = f3.w - f3.x; ey[4] = f4.x - f3.y; ez[4] = f4.y - f3.z;
        ex[5] = f4.z - f3.w; ey[5] = f4.w - f4.x; ez[5] = f5.x - f4.y;
        ex[6] = f5.y - f4.z; ey[6] = f5.z - f4.w; ez[6] = f5.w - f5.x;

        // ---- packed params (6 aligned LDG.128, L2-resident) ----
        float4 c0 = g_prm[0 * NGROUPS + g];
        float4 c1 = g_prm[1 * NGROUPS + g];
        float4 c2 = g_prm[2 * NGROUPS + g];
        float4 c3 = g_prm[3 * NGROUPS + g];
        float4 c4 = g_prm[4 * NGROUPS + g];
        float4 c5 = g_prm[5 * NGROUPS + g];
        const float* pc0 = (const float*)&c0; const float* pc1 = (const float*)&c1;
        const float* pc2 = (const float*)&c2; const float* pc3 = (const float*)&c3;
        const float* pc4 = (const float*)&c4; const float* pc5 = (const float*)&c5;

        // ---- rolling window over rows r = 4g+j, j=1..4 ----
        float Rc = rsqrt_ap(fmaf(ex[2],ex[2], fmaf(ey[2],ey[2], ez[2]*ez[2])));
        float Dp = fmaf(ex[1],ex[2], fmaf(ey[1],ey[2], ez[1]*ez[2]));

        float res[12];
#pragma unroll
        for (int j = 1; j <= 4; j++) {
            float pxc = ex[j],   pyc = ey[j],   pzc = ez[j];     // prev = e_j
            float cxe = ex[j+1], cye = ey[j+1], cze = ez[j+1];   // cur  = e_{j+1}
            float nxe = ex[j+2], nye = ey[j+2], nze = ez[j+2];   // next = e_{j+2}

            float Sn = fmaf(nxe,nxe, fmaf(nye,nye, nze*nze));
            float Rn = rsqrt_ap(Sn);
            float Dc = fmaf(cxe,nxe, fmaf(cye,nye, cze*nze));

            float bond = Sn * Rn;

            float cosang = fminf(fmaxf(-Dc * Rc * Rn, -1.0f), 1.0f);
            float ang = acos_fast(cosang);

            float inv = Rc * Rc;                 // 1/|e_cur|^2
            float f0c = Dp * inv;
            float f1c = Dc * inv;
            // v' = prev - f0*cur (true v = -v');  w = next - f1*cur
            float vx = fmaf(-f0c, cxe, pxc), vy = fmaf(-f0c, cye, pyc), vz = fmaf(-f0c, cze, pzc);
            float wx = fmaf(-f1c, cxe, nxe), wy = fmaf(-f1c, cye, nye), wz = fmaf(-f1c, cze, nze);

            float xx = -fmaf(vx,wx, fmaf(vy,wy, vz*wz));
            float cxx = fmaf(cye,vz, -cze*vy);
            float cyy = fmaf(cze,vx, -cxe*vz);
            float czz = fmaf(cxe,vy, -cye*vx);
            float yy = Rc * fmaf(cxx,wx, fmaf(cyy,wy, czz*wz));
            float dihe = atan2_fast(yy, xx);

            // normalize with packed params (pure fma)
            res[3*(j-1)]   = fmaf(bond, pc0[j-1], pc1[j-1]);
            res[3*(j-1)+1] = fmaf(ang,  pc2[j-1], pc3[j-1]);
            float dd = dihe - pc4[j-1];
            dd = (dd < -PI_F) ? dd + TWO_PI : dd;
            dd = (dd >  PI_F) ? dd - TWO_PI : dd;
            res[3*(j-1)+2] = dd * pc5[j-1];

            Rc = Rn; Dp = Dc;
        }

        outv[3*g + 3] = make_float4(res[0], res[1], res[2],  res[3]);
        outv[3*g + 4] = make_float4(res[4], res[5], res[6],  res[7]);
        outv[3*g + 5] = make_float4(res[8], res[9], res[10], res[11]);
    }

    // Row 0 + head (floats 0..11): one thread, 3 aligned STG.128.
    if (tid == 255) {
        float bond, ang, dihe;
        ic_row(A, bond, ang, dihe);
        float ob = (bond - __ldg(mb)) * rcp_ap(__ldg(sb));
        float oa = (ang  - __ldg(ma)) * rcp_ap(__ldg(sa));
        float dd = dihe - __ldg(md);
        dd = (dd < -PI_F) ? dd + TWO_PI : dd;
        dd = (dd >  PI_F) ? dd - TWO_PI : dd;
        float od = dd * rcp_ap(__ldg(sd));
        outv[0] = make_float4(A[0], A[1], A[2], A[3]);
        outv[1] = make_float4(A[4], A[5], A[6], A[7]);
        outv[2] = make_float4(A[8], ob, oa, od);
    }
}

extern "C" void kernel_launch(void* const* d_in, const int* in_sizes, int n_in,
                              void* d_out, int out_size)
{
    const float* x  = (const float*)d_in[0];
    const float* mb = (const float*)d_in[2];
    const float* sb = (const float*)d_in[3];
    const float* ma = (const float*)d_in[4];
    const float* sa = (const float*)d_in[5];
    const float* md = (const float*)d_in[6];
    const float* sd = (const float*)d_in[7];

    int bsz = in_sizes[0] / NDIM;   // 2048

    prep_kernel<<<(NGROUPS + 255) / 256, 256>>>(mb, sb, ma, sa, md, sd);
    ict_kernel<<<bsz, 256>>>(x, mb, sb, ma, sa, md, sd, (float*)d_out);
}